// round 5
// baseline (speedup 1.0000x reference)
#include <cuda_runtime.h>
#include <cuda_bf16.h>

// CrossHeadOnlineHadamardHook: 32-point Walsh-Hadamard across heads.
// x: (T, 4096) fp32 rows, T = 16384. heads = 32, HEAD_DIM = 128.
// For each (t, d): v[h] = x[t*4096 + h*128 + d], v = H32 * v / sqrt(32).
//
// One thread owns one (token, d-pair): 32 coalesced LDG.64 (256B/warp
// transactions, 512B head stride), register FWHT, 32 coalesced STG.64.
// R3 change: streaming cache hints (__ldcs/__stcs, evict-first) on both
// the read and write streams — data is strictly read-once/write-once
// (536 MB >> 126 MB L2), so default evict-normal policy only pollutes L2
// and makes dirty-line writeback bursty at the DRAM scheduler.

#define NUM_HEADS 32
#define HEAD_DIM  128
#define HIDDEN    (NUM_HEADS * HEAD_DIM)      // 4096
#define PAIRS_PER_ROW (HIDDEN / 2)            // 2048 float2 per token row
#define HPAIR_STRIDE (HEAD_DIM / 2)           // 64 float2 between heads

__global__ __launch_bounds__(256)
void had32_crosshead_kernel(const float* __restrict__ x,
                            float* __restrict__ out,
                            int n_threads_total)
{
    int tid = blockIdx.x * 256 + threadIdx.x;
    if (tid >= n_threads_total) return;

    int t  = tid >> 6;          // token index (64 d-pairs per token)
    int dp = tid & 63;          // which float2 within the head dim

    size_t base = (size_t)t * PAIRS_PER_ROW + dp;
    const float2* __restrict__ px = reinterpret_cast<const float2*>(x) + base;
    float2*       __restrict__ py = reinterpret_cast<float2*>(out) + base;

    float2 v[NUM_HEADS];

    // 32 coalesced LDG.64, evict-first (no reuse)
#pragma unroll
    for (int h = 0; h < NUM_HEADS; ++h) {
        v[h] = __ldcs(px + (size_t)h * HPAIR_STRIDE);
    }

    // In-register 32-point FWHT (natural order; stage order irrelevant)
#pragma unroll
    for (int s = 1; s < NUM_HEADS; s <<= 1) {
#pragma unroll
        for (int i = 0; i < NUM_HEADS; ++i) {
            if ((i & s) == 0) {
                float2 a = v[i];
                float2 b = v[i + s];
                v[i].x     = a.x + b.x;
                v[i].y     = a.y + b.y;
                v[i + s].x = a.x - b.x;
                v[i + s].y = a.y - b.y;
            }
        }
    }

    const float scl = 0.17677669529663687f;   // 1/sqrt(32)

    // 32 coalesced STG.64, evict-first (never re-read)
#pragma unroll
    for (int h = 0; h < NUM_HEADS; ++h) {
        float2 r;
        r.x = v[h].x * scl;
        r.y = v[h].y * scl;
        __stcs(py + (size_t)h * HPAIR_STRIDE, r);
    }
}

extern "C" void kernel_launch(void* const* d_in, const int* in_sizes, int n_in,
                              void* d_out, int out_size)
{
    const float* x = (const float*)d_in[0];
    float* out = (float*)d_out;

    int n = in_sizes[0];                 // total fp32 elements (4*4096*4096)
    int n_threads = n >> 6;              // each thread handles 64 elements
    int blocks = (n_threads + 255) / 256;

    had32_crosshead_kernel<<<blocks, 256>>>(x, out, n_threads);
}

// round 6
// speedup vs baseline: 1.0031x; 1.0031x over previous
#include <cuda_runtime.h>
#include <cuda_bf16.h>

// CrossHeadOnlineHadamardHook: 32-point Walsh-Hadamard across heads.
// x: (T, 4096) fp32 rows, T = 16384. heads = 32, HEAD_DIM = 128.
// For each (t, d): v[h] = x[t*4096 + h*128 + d], v = H32 * v / sqrt(32).
//
// One thread owns one (token, d-pair): 32 coalesced LDG.64 (256B/warp
// transactions, 512B head stride), register FWHT, 32 coalesced STG.64.
// R3 change: streaming cache hints (__ldcs/__stcs, evict-first) on both
// the read and write streams — data is strictly read-once/write-once
// (536 MB >> 126 MB L2), so default evict-normal policy only pollutes L2
// and makes dirty-line writeback bursty at the DRAM scheduler.

#define NUM_HEADS 32
#define HEAD_DIM  128
#define HIDDEN    (NUM_HEADS * HEAD_DIM)      // 4096
#define PAIRS_PER_ROW (HIDDEN / 2)            // 2048 float2 per token row
#define HPAIR_STRIDE (HEAD_DIM / 2)           // 64 float2 between heads

__global__ __launch_bounds__(256)
void had32_crosshead_kernel(const float* __restrict__ x,
                            float* __restrict__ out,
                            int n_threads_total)
{
    int tid = blockIdx.x * 256 + threadIdx.x;
    if (tid >= n_threads_total) return;

    int t  = tid >> 6;          // token index (64 d-pairs per token)
    int dp = tid & 63;          // which float2 within the head dim

    size_t base = (size_t)t * PAIRS_PER_ROW + dp;
    const float2* __restrict__ px = reinterpret_cast<const float2*>(x) + base;
    float2*       __restrict__ py = reinterpret_cast<float2*>(out) + base;

    float2 v[NUM_HEADS];

    // 32 coalesced LDG.64, evict-first (no reuse)
#pragma unroll
    for (int h = 0; h < NUM_HEADS; ++h) {
        v[h] = __ldcs(px + (size_t)h * HPAIR_STRIDE);
    }

    // In-register 32-point FWHT (natural order; stage order irrelevant)
#pragma unroll
    for (int s = 1; s < NUM_HEADS; s <<= 1) {
#pragma unroll
        for (int i = 0; i < NUM_HEADS; ++i) {
            if ((i & s) == 0) {
                float2 a = v[i];
                float2 b = v[i + s];
                v[i].x     = a.x + b.x;
                v[i].y     = a.y + b.y;
                v[i + s].x = a.x - b.x;
                v[i + s].y = a.y - b.y;
            }
        }
    }

    const float scl = 0.17677669529663687f;   // 1/sqrt(32)

    // 32 coalesced STG.64, evict-first (never re-read)
#pragma unroll
    for (int h = 0; h < NUM_HEADS; ++h) {
        float2 r;
        r.x = v[h].x * scl;
        r.y = v[h].y * scl;
        __stcs(py + (size_t)h * HPAIR_STRIDE, r);
    }
}

extern "C" void kernel_launch(void* const* d_in, const int* in_sizes, int n_in,
                              void* d_out, int out_size)
{
    const float* x = (const float*)d_in[0];
    float* out = (float*)d_out;

    int n = in_sizes[0];                 // total fp32 elements (4*4096*4096)
    int n_threads = n >> 6;              // each thread handles 64 elements
    int blocks = (n_threads + 255) / 256;

    had32_crosshead_kernel<<<blocks, 256>>>(x, out, n_threads);
}

// round 7
// speedup vs baseline: 1.0066x; 1.0035x over previous
#include <cuda_runtime.h>
#include <cuda_bf16.h>

// CrossHeadOnlineHadamardHook: 32-point Walsh-Hadamard across heads.
// x: (T, 4096) fp32 rows, T = 16384. heads = 32, HEAD_DIM = 128.
// For each (t, d): v[h] = x[t*4096 + h*128 + d], v = H32 * v / sqrt(32).
//
// R6: float4 per thread (LDG.128/STG.128). One thread owns one
// (token, d-quad): 32 x 512B-per-warp coalesced loads (16KB read burst
// per warp), register FWHT over 32 float4 lanes, 32 coalesced 512B
// stores. Halves memory-instruction count and doubles per-stream burst
// length vs the float2 version; occupancy drop (~160 regs) is irrelevant
// since in-flight bytes (~130KB/SM) vastly exceed the latency-hiding
// requirement (~10KB/SM).

#define NUM_HEADS 32
#define HEAD_DIM  128
#define HIDDEN    (NUM_HEADS * HEAD_DIM)      // 4096
#define QUADS_PER_ROW (HIDDEN / 4)            // 1024 float4 per token row
#define QUADS_PER_TOKEN (HEAD_DIM / 4)        // 32 threads per token
#define HQUAD_STRIDE (HEAD_DIM / 4)           // 32 float4 between heads

__global__ __launch_bounds__(128)
void had32_crosshead_f4_kernel(const float* __restrict__ x,
                               float* __restrict__ out,
                               int n_threads_total)
{
    int tid = blockIdx.x * 128 + threadIdx.x;
    if (tid >= n_threads_total) return;

    int t = tid >> 5;           // token index (32 quads per token)
    int q = tid & 31;           // which float4 within the head dim

    size_t base = (size_t)t * QUADS_PER_ROW + q;
    const float4* __restrict__ px = reinterpret_cast<const float4*>(x) + base;
    float4*       __restrict__ py = reinterpret_cast<float4*>(out) + base;

    float4 v[NUM_HEADS];

    // 32 coalesced LDG.128 (512B/warp), evict-first streaming
#pragma unroll
    for (int h = 0; h < NUM_HEADS; ++h) {
        v[h] = __ldcs(px + (size_t)h * HQUAD_STRIDE);
    }

    // In-register 32-point FWHT over 4 independent lanes
#pragma unroll
    for (int s = 1; s < NUM_HEADS; s <<= 1) {
#pragma unroll
        for (int i = 0; i < NUM_HEADS; ++i) {
            if ((i & s) == 0) {
                float4 a = v[i];
                float4 b = v[i + s];
                v[i].x     = a.x + b.x;
                v[i].y     = a.y + b.y;
                v[i].z     = a.z + b.z;
                v[i].w     = a.w + b.w;
                v[i + s].x = a.x - b.x;
                v[i + s].y = a.y - b.y;
                v[i + s].z = a.z - b.z;
                v[i + s].w = a.w - b.w;
            }
        }
    }

    const float scl = 0.17677669529663687f;   // 1/sqrt(32)

    // 32 coalesced STG.128, evict-first
#pragma unroll
    for (int h = 0; h < NUM_HEADS; ++h) {
        float4 r;
        r.x = v[h].x * scl;
        r.y = v[h].y * scl;
        r.z = v[h].z * scl;
        r.w = v[h].w * scl;
        __stcs(py + (size_t)h * HQUAD_STRIDE, r);
    }
}

extern "C" void kernel_launch(void* const* d_in, const int* in_sizes, int n_in,
                              void* d_out, int out_size)
{
    const float* x = (const float*)d_in[0];
    float* out = (float*)d_out;

    int n = in_sizes[0];                 // total fp32 elements (4*4096*4096)
    int n_threads = n >> 7;              // each thread handles 128 floats
    int blocks = (n_threads + 127) / 128;

    had32_crosshead_f4_kernel<<<blocks, 128>>>(x, out, n_threads);
}